// round 14
// baseline (speedup 1.0000x reference)
#include <cuda_runtime.h>
#include <cuda_bf16.h>
#include <cstdint>

#define DIM 768
#define NH 12
#define DH 64
#define BATCH 4
#define SEQ 1024
#define ROWS (BATCH*SEQ)            // 4096
#define QSCALE 0.18033688011112042f // 0.125 * log2(e), folded into Q epilogue

// ---------------- scratch ----------------
__device__ __nv_bfloat16 g_xn [ROWS*DIM];
__device__ __nv_bfloat16 g_q  [ROWS*DIM];
__device__ __nv_bfloat16 g_k  [ROWS*DIM];
__device__ __nv_bfloat16 g_v  [ROWS*DIM];
__device__ __nv_bfloat16 g_att[ROWS*DIM];
__device__ __nv_bfloat16 g_wb [4 * DIM * DIM];   // bf16 weights: q,k,v,proj

// ---------------- helpers ----------------
__device__ __forceinline__ uint32_t saddr(const void* p) {
    return (uint32_t)__cvta_generic_to_shared(p);
}
__device__ __forceinline__ void cp16(void* s, const void* g) {
    asm volatile("cp.async.cg.shared.global [%0], [%1], 16;\n"
                 :: "r"(saddr(s)), "l"(g));
}
__device__ __forceinline__ void cp_commit() {
    asm volatile("cp.async.commit_group;\n");
}
__device__ __forceinline__ void ldsm4(uint32_t* r, uint32_t a) {
    asm volatile("ldmatrix.sync.aligned.m8n8.x4.shared.b16 {%0,%1,%2,%3}, [%4];"
                 : "=r"(r[0]), "=r"(r[1]), "=r"(r[2]), "=r"(r[3]) : "r"(a));
}
__device__ __forceinline__ void ldsm4t(uint32_t* r, uint32_t a) {
    asm volatile("ldmatrix.sync.aligned.m8n8.x4.trans.shared.b16 {%0,%1,%2,%3}, [%4];"
                 : "=r"(r[0]), "=r"(r[1]), "=r"(r[2]), "=r"(r[3]) : "r"(a));
}
__device__ __forceinline__ void mma16816(float* d, const uint32_t* a, const uint32_t* b) {
    asm volatile("mma.sync.aligned.m16n8k16.row.col.f32.bf16.bf16.f32 "
        "{%0,%1,%2,%3}, {%4,%5,%6,%7}, {%8,%9}, {%0,%1,%2,%3};\n"
        : "+f"(d[0]), "+f"(d[1]), "+f"(d[2]), "+f"(d[3])
        : "r"(a[0]), "r"(a[1]), "r"(a[2]), "r"(a[3]), "r"(b[0]), "r"(b[1]));
}
__device__ __forceinline__ uint32_t packbf(float lo, float hi) {
    __nv_bfloat162 h = __floats2bfloat162_rn(lo, hi);
    return *reinterpret_cast<uint32_t*>(&h);
}
__device__ __forceinline__ float ex2(float x) {
    float y;
    asm("ex2.approx.ftz.f32 %0, %1;" : "=f"(y) : "f"(x));
    return y;
}

// ---------------- fused LayerNorm (ddof=1) + weight cvt ----------------
#define CVTBLKS (4 * DIM * DIM / (384 * 4))   // 1536
__global__ void __launch_bounds__(384) ln_cvt(const float* __restrict__ x,
                                              __nv_bfloat16* __restrict__ xn,
                                              const float* __restrict__ w0,
                                              const float* __restrict__ w1,
                                              const float* __restrict__ w2,
                                              const float* __restrict__ w3,
                                              __nv_bfloat16* __restrict__ wb) {
    int t = threadIdx.x;
    if (blockIdx.x >= ROWS) {
        int i = ((blockIdx.x - ROWS) * 384 + t) * 4;      // [0, 4*DIM*DIM)
        int m = i / (DIM * DIM);
        int r = i - m * (DIM * DIM);
        const float* s = m == 0 ? w0 : m == 1 ? w1 : m == 2 ? w2 : w3;
        float4 v = *(const float4*)(s + r);
        uint2 o;
        o.x = packbf(v.x, v.y);
        o.y = packbf(v.z, v.w);
        *(uint2*)(wb + i) = o;
        return;
    }
    int row = blockIdx.x;
    float2 v = *(const float2*)(x + (size_t)row * DIM + 2 * t);
    float s  = v.x + v.y;
    float sq = v.x * v.x + v.y * v.y;
    #pragma unroll
    for (int o = 16; o; o >>= 1) {
        s  += __shfl_xor_sync(0xffffffffu, s,  o);
        sq += __shfl_xor_sync(0xffffffffu, sq, o);
    }
    __shared__ float rs[12], rq[12];
    int w = t >> 5, l = t & 31;
    if (l == 0) { rs[w] = s; rq[w] = sq; }
    __syncthreads();
    if (w == 0) {
        s  = (l < 12) ? rs[l] : 0.f;
        sq = (l < 12) ? rq[l] : 0.f;
        #pragma unroll
        for (int o = 16; o; o >>= 1) {
            s  += __shfl_xor_sync(0xffffffffu, s,  o);
            sq += __shfl_xor_sync(0xffffffffu, sq, o);
        }
        if (l == 0) { rs[0] = s; rq[0] = sq; }
    }
    __syncthreads();
    s = rs[0]; sq = rq[0];
    float mean = s * (1.f / DIM);
    float var  = (sq - (float)DIM * mean * mean) * (1.f / (DIM - 1));
    float inv  = rsqrtf(var);
    ((uint32_t*)xn)[(size_t)row * (DIM / 2) + t] =
        packbf((v.x - mean) * inv, (v.y - mean) * inv);
}

// ---------------- bf16 GEMM-NT: BM=128 BN=64 BK=32, warp tile 64x32 ---------
// 128 threads (4 warps, 2m x 2n), warp tile 64x32: 6 LDSM feed 16 MMAs per
// k-step (ratio 2.67 vs 2.0) - shorter LDSM chain per MMA. 5 CTAs/SM target.
#define NKT (DIM / 32)            // 24
#define ASZ (128 * 40)            // A stage elems
#define BSZ (64 * 40)             // B stage elems
#define SMEM_GEMM (2 * (ASZ + BSZ) * 2)   // 30720 B
__global__ void __launch_bounds__(128, 5) gemm_bf(
        const __nv_bfloat16* __restrict__ A,
        const __nv_bfloat16* __restrict__ Wall,
        const float* __restrict__ b0, const float* __restrict__ b1,
        const float* __restrict__ b2,
        __nv_bfloat16* __restrict__ c0, __nv_bfloat16* __restrict__ c1,
        __nv_bfloat16* __restrict__ c2,
        const float* __restrict__ res, float* __restrict__ outF,
        int mode) {
    extern __shared__ __nv_bfloat16 gsm[];
    __nv_bfloat16* Asb = gsm;             // [2][128][40]
    __nv_bfloat16* Bsb = gsm + 2 * ASZ;   // [2][64][40]

    int nb, sel;
    if (mode == 0) { sel = blockIdx.x / 12; nb = blockIdx.x % 12; }
    else           { sel = 3;               nb = blockIdx.x; }
    const __nv_bfloat16* W = Wall + (size_t)sel * DIM * DIM;
    const float* bias = mode == 0 ? (sel == 0 ? b0 : sel == 1 ? b1 : b2) : b0;
    __nv_bfloat16* Cb = sel == 0 ? c0 : sel == 1 ? c1 : c2;
    float oscale = (mode == 0 && sel == 0) ? QSCALE : 1.0f;

    int bm0 = blockIdx.y * 128, bn0 = nb * 64;
    int tid = threadIdx.x, lane = tid & 31, wid = tid >> 5;
    int g = lane >> 2, tq = lane & 3;
    int wm = (wid >> 1) * 64, wn = (wid & 1) * 32;   // warp tile 64x32

    // loaders: A row per thread (4 cp16); B row per 2 threads (2 cp16)
    int lrA = tid,       lkA = 0;
    int lrB = tid >> 1,  lkB = (tid & 1) * 16;
    const __nv_bfloat16* Ag = A + (size_t)(bm0 + lrA) * DIM;
    const __nv_bfloat16* Wg = W + (size_t)(bn0 + lrB) * DIM + lkB;

    float acc[4][4][4] = {};

    // prefetch tile 0 into stage 0
    {
        __nv_bfloat16* as = Asb + lrA * 40;
        __nv_bfloat16* bs = Bsb + lrB * 40 + lkB;
        #pragma unroll
        for (int c = 0; c < 4; c++) cp16(as + 8 * c, Ag + 8 * c);
        cp16(bs,     Wg);
        cp16(bs + 8, Wg + 8);
        cp_commit();
    }

    for (int kt = 0; kt < NKT; kt++) {
        int s = kt & 1;
        asm volatile("cp.async.wait_group 0;\n");
        __syncthreads();   // tile kt visible; stage s^1 readers (kt-1) done
        if (kt + 1 < NKT) {
            __nv_bfloat16* as = Asb + (s ^ 1) * ASZ + lrA * 40;
            __nv_bfloat16* bs = Bsb + (s ^ 1) * BSZ + lrB * 40 + lkB;
            const __nv_bfloat16* ag = Ag + (kt + 1) * 32;
            const __nv_bfloat16* wg = Wg + (kt + 1) * 32;
            #pragma unroll
            for (int c = 0; c < 4; c++) cp16(as + 8 * c, ag + 8 * c);
            cp16(bs,     wg);
            cp16(bs + 8, wg + 8);
            cp_commit();
        }

        uint32_t aA = saddr(Asb + s * ASZ + (wm + (lane & 15)) * 40
                            + (lane >> 4) * 8);
        uint32_t aB = saddr(Bsb + s * BSZ
                            + (wn + (lane & 7) + ((lane >> 4) & 1) * 8) * 40
                            + ((lane >> 3) & 1) * 8);
        #pragma unroll
        for (int ks = 0; ks < 2; ks++) {
            uint32_t a[4][4], b[2][4];
            #pragma unroll
            for (int mt = 0; mt < 4; mt++)
                ldsm4(a[mt], aA + mt * (16 * 80) + ks * 32);
            #pragma unroll
            for (int nt = 0; nt < 2; nt++)
                ldsm4(b[nt], aB + nt * (16 * 80) + ks * 32);
            #pragma unroll
            for (int mt = 0; mt < 4; mt++) {
                #pragma unroll
                for (int nt = 0; nt < 2; nt++) {
                    mma16816(acc[mt][2 * nt],     a[mt], b[nt]);
                    mma16816(acc[mt][2 * nt + 1], a[mt], b[nt] + 2);
                }
            }
        }
    }

    #pragma unroll
    for (int mt = 0; mt < 4; mt++) {
        int row = bm0 + wm + 16 * mt + g;
        #pragma unroll
        for (int j = 0; j < 4; j++) {
            int col = bn0 + wn + 8 * j + 2 * tq;
            float bx = bias[col], by = bias[col + 1];
            size_t o0 = (size_t)row * DIM + col;
            size_t o1 = (size_t)(row + 8) * DIM + col;
            if (mode == 0) {
                *(uint32_t*)(Cb + o0) = packbf((acc[mt][j][0] + bx) * oscale,
                                               (acc[mt][j][1] + by) * oscale);
                *(uint32_t*)(Cb + o1) = packbf((acc[mt][j][2] + bx) * oscale,
                                               (acc[mt][j][3] + by) * oscale);
            } else {
                float2 e0 = *(const float2*)(res + o0);
                float2 e1 = *(const float2*)(res + o1);
                *(float2*)(outF + o0) = make_float2(acc[mt][j][0] + bx + e0.x,
                                                    acc[mt][j][1] + by + e0.y);
                *(float2*)(outF + o1) = make_float2(acc[mt][j][2] + bx + e1.x,
                                                    acc[mt][j][3] + by + e1.y);
            }
        }
    }
}

// ---------------- bf16 flash attention: P in registers (R9 winner) ----------
#define KTILE 4608              // 64*72 elems
#define QTILE 9216              // 128*72 elems
#define SMEM_ATTN ((QTILE + 4 * KTILE) * 2)
__global__ void __launch_bounds__(256) attn_tc(const __nv_bfloat16* __restrict__ Q,
                                               const __nv_bfloat16* __restrict__ K,
                                               const __nv_bfloat16* __restrict__ V,
                                               __nv_bfloat16* __restrict__ O) {
    extern __shared__ __nv_bfloat16 smb[];
    __nv_bfloat16* sQ = smb;                       // 128 x 72
    __nv_bfloat16* sK = smb + QTILE;               // 2 x 64 x 72
    __nv_bfloat16* sV = smb + QTILE + 2 * KTILE;   // 2 x 64 x 72

    int qt = blockIdx.x, h = blockIdx.y, b = blockIdx.z;
    int tid = threadIdx.x, lane = tid & 31, wid = tid >> 5;
    int g = lane >> 2, tq = lane & 3;
    int m0 = wid * 16;

    int qlr = tid >> 1, qlk = (tid & 1) * 32;   // Q loader
    int klr = tid >> 2, klk = (tid & 3) * 16;   // K/V loader

    const __nv_bfloat16* Kg = K + (size_t)(b * SEQ + klr) * DIM + h * DH + klk;
    const __nv_bfloat16* Vg = V + (size_t)(b * SEQ + klr) * DIM + h * DH + klk;

    // Q tile copy (already scaled by QSCALE in GEMM)
    {
        const uint4* qp = (const uint4*)(Q + (size_t)(b * SEQ + qt * 128 + qlr) * DIM
                                           + h * DH + qlk);
        uint4* dq = (uint4*)&sQ[qlr * 72 + qlk];
        #pragma unroll
        for (int u = 0; u < 4; u++) dq[u] = qp[u];
    }

    // prefetch K/V tile 0 into stage 0
    cp16(&sK[klr * 72 + klk],     Kg);
    cp16(&sK[klr * 72 + klk + 8], Kg + 8);
    cp16(&sV[klr * 72 + klk],     Vg);
    cp16(&sV[klr * 72 + klk + 8], Vg + 8);
    cp_commit();

    uint32_t aQ = saddr(&sQ[(m0 + (lane & 15)) * 72 + (lane >> 4) * 8]);
    uint32_t aK0 = saddr(&sK[((lane & 7) + ((lane >> 4) & 1) * 8) * 72
                             + ((lane >> 3) & 1) * 8]);
    uint32_t aV0 = saddr(&sV[((lane & 7) + ((lane >> 3) & 1) * 8) * 72
                             + (lane >> 4) * 8]);

    __syncthreads();   // Q tile visible to all warps

    uint32_t qf[4][4];
    #pragma unroll
    for (int ks = 0; ks < 4; ks++) ldsm4(qf[ks], aQ + ks * 32);

    float m0r = -1e30f, m1r = -1e30f, l0r = 0.f, l1r = 0.f;
    float o[8][4] = {};

    for (int kt = 0; kt < SEQ / 64; kt++) {
        int s = kt & 1;
        asm volatile("cp.async.wait_group 0;\n");
        __syncthreads();   // stage s ready; stage s^1 readers (iter kt-1) done
        if (kt + 1 < SEQ / 64) {
            int so = (s ^ 1) * KTILE;
            const __nv_bfloat16* kg = Kg + (size_t)(kt + 1) * 64 * DIM;
            const __nv_bfloat16* vg = Vg + (size_t)(kt + 1) * 64 * DIM;
            cp16(&sK[so + klr * 72 + klk],     kg);
            cp16(&sK[so + klr * 72 + klk + 8], kg + 8);
            cp16(&sV[so + klr * 72 + klk],     vg);
            cp16(&sV[so + klr * 72 + klk + 8], vg + 8);
            cp_commit();
        }

        uint32_t aK = aK0 + s * (KTILE * 2);
        uint32_t aV = aV0 + s * (KTILE * 2);

        // S = Q K^T (warp's 16 rows x 64 keys); sc[j] = key cols 8j..8j+7
        float sc[8][4] = {};
        #pragma unroll
        for (int ks = 0; ks < 4; ks++) {
            #pragma unroll
            for (int j2 = 0; j2 < 4; j2++) {
                uint32_t bb[4];
                ldsm4(bb, aK + j2 * (16 * 144) + ks * 32);
                mma16816(sc[2 * j2],     qf[ks], bb);
                mma16816(sc[2 * j2 + 1], qf[ks], bb + 2);
            }
        }

        // online softmax, base-2 domain (Q pre-scaled by 0.125*log2e)
        float mx0 = -1e30f, mx1 = -1e30f;
        #pragma unroll
        for (int j = 0; j < 8; j++) {
            mx0 = fmaxf(mx0, fmaxf(sc[j][0], sc[j][1]));
            mx1 = fmaxf(mx1, fmaxf(sc[j][2], sc[j][3]));
        }
        mx0 = fmaxf(mx0, __shfl_xor_sync(0xffffffffu, mx0, 1));
        mx0 = fmaxf(mx0, __shfl_xor_sync(0xffffffffu, mx0, 2));
        mx1 = fmaxf(mx1, __shfl_xor_sync(0xffffffffu, mx1, 1));
        mx1 = fmaxf(mx1, __shfl_xor_sync(0xffffffffu, mx1, 2));
        float mn0 = fmaxf(m0r, mx0), mn1 = fmaxf(m1r, mx1);
        float al0 = ex2(m0r - mn0), al1 = ex2(m1r - mn1);
        float ls0 = 0.f, ls1 = 0.f;
        #pragma unroll
        for (int j = 0; j < 8; j++) {
            sc[j][0] = ex2(sc[j][0] - mn0); ls0 += sc[j][0];
            sc[j][1] = ex2(sc[j][1] - mn0); ls0 += sc[j][1];
            sc[j][2] = ex2(sc[j][2] - mn1); ls1 += sc[j][2];
            sc[j][3] = ex2(sc[j][3] - mn1); ls1 += sc[j][3];
        }
        ls0 += __shfl_xor_sync(0xffffffffu, ls0, 1);
        ls0 += __shfl_xor_sync(0xffffffffu, ls0, 2);
        ls1 += __shfl_xor_sync(0xffffffffu, ls1, 1);
        ls1 += __shfl_xor_sync(0xffffffffu, ls1, 2);
        l0r = l0r * al0 + ls0;  m0r = mn0;
        l1r = l1r * al1 + ls1;  m1r = mn1;
        #pragma unroll
        for (int j = 0; j < 8; j++) {
            o[j][0] *= al0; o[j][1] *= al0;
            o[j][2] *= al1; o[j][3] *= al1;
        }

        // O += P V : P packed straight from S fragments (no smem round-trip)
        #pragma unroll
        for (int ks = 0; ks < 4; ks++) {
            uint32_t a[4];
            a[0] = packbf(sc[2 * ks][0],     sc[2 * ks][1]);
            a[1] = packbf(sc[2 * ks][2],     sc[2 * ks][3]);
            a[2] = packbf(sc[2 * ks + 1][0], sc[2 * ks + 1][1]);
            a[3] = packbf(sc[2 * ks + 1][2], sc[2 * ks + 1][3]);
            #pragma unroll
            for (int j2 = 0; j2 < 4; j2++) {
                uint32_t bb[4];
                ldsm4t(bb, aV + ks * (16 * 144) + j2 * 32);
                mma16816(o[2 * j2],     a, bb);
                mma16816(o[2 * j2 + 1], a, bb + 2);
            }
        }
    }

    float inv0 = 1.f / l0r, inv1 = 1.f / l1r;
    int row0 = b * SEQ + qt * 128 + m0 + g;
    #pragma unroll
    for (int j = 0; j < 8; j++) {
        int col = h * DH + 8 * j + 2 * tq;
        *(uint32_t*)(O + (size_t)row0 * DIM + col) =
            packbf(o[j][0] * inv0, o[j][1] * inv0);
        *(uint32_t*)(O + (size_t)(row0 + 8) * DIM + col) =
            packbf(o[j][2] * inv1, o[j][3] * inv1);
    }
}

// ---------------- launch ----------------
extern "C" void kernel_launch(void* const* d_in, const int* in_sizes, int n_in,
                              void* d_out, int out_size) {
    const float* x  = (const float*)d_in[0];
    const float* qw = (const float*)d_in[1];
    const float* kw = (const float*)d_in[2];
    const float* vw = (const float*)d_in[3];
    const float* qb = (const float*)d_in[4];
    const float* kb = (const float*)d_in[5];
    const float* vb = (const float*)d_in[6];
    const float* pw = (const float*)d_in[7];
    const float* pb = (const float*)d_in[8];
    float* out = (float*)d_out;

    __nv_bfloat16 *xn, *q, *k, *v, *att, *wb;
    cudaGetSymbolAddress((void**)&xn,  g_xn);
    cudaGetSymbolAddress((void**)&q,   g_q);
    cudaGetSymbolAddress((void**)&k,   g_k);
    cudaGetSymbolAddress((void**)&v,   g_v);
    cudaGetSymbolAddress((void**)&att, g_att);
    cudaGetSymbolAddress((void**)&wb,  g_wb);

    cudaFuncSetAttribute(attn_tc,
                         cudaFuncAttributeMaxDynamicSharedMemorySize, SMEM_ATTN);
    cudaFuncSetAttribute(gemm_bf,
                         cudaFuncAttributeMaxDynamicSharedMemorySize, SMEM_GEMM);

    // fused LayerNorm + weight conversion
    ln_cvt<<<ROWS + CVTBLKS, 384>>>(x, xn, qw, kw, vw, pw, wb);

    // QKV: 36 x 32 blocks (sel = x/12); q output pre-scaled by QSCALE
    gemm_bf<<<dim3(36, 32), 128, SMEM_GEMM>>>(xn, wb, qb, kb, vb, q, k, v,
                                              nullptr, nullptr, 0);

    attn_tc<<<dim3(SEQ / 128, NH, BATCH), 256, SMEM_ATTN>>>(q, k, v, att);

    // proj: 12 x 32 blocks, fp32 out + bias + residual
    gemm_bf<<<dim3(12, 32), 128, SMEM_GEMM>>>(att, wb, pb, nullptr, nullptr,
                                              nullptr, nullptr, nullptr, x, out, 1);
}

// round 15
// speedup vs baseline: 1.1885x; 1.1885x over previous
#include <cuda_runtime.h>
#include <cuda_bf16.h>
#include <cstdint>

#define DIM 768
#define NH 12
#define DH 64
#define BATCH 4
#define SEQ 1024
#define ROWS (BATCH*SEQ)            // 4096
#define QSCALE 0.18033688011112042f // 0.125 * log2(e), folded into Q epilogue

// ---------------- scratch ----------------
__device__ __nv_bfloat16 g_xn [ROWS*DIM];
__device__ __nv_bfloat16 g_q  [ROWS*DIM];
__device__ __nv_bfloat16 g_k  [ROWS*DIM];
__device__ __nv_bfloat16 g_v  [ROWS*DIM];
__device__ __nv_bfloat16 g_att[ROWS*DIM];
__device__ __nv_bfloat16 g_wb [4 * DIM * DIM];   // bf16 weights: q,k,v,proj

// ---------------- helpers ----------------
__device__ __forceinline__ uint32_t saddr(const void* p) {
    return (uint32_t)__cvta_generic_to_shared(p);
}
__device__ __forceinline__ void cp16(void* s, const void* g) {
    asm volatile("cp.async.cg.shared.global [%0], [%1], 16;\n"
                 :: "r"(saddr(s)), "l"(g));
}
__device__ __forceinline__ void cp_commit() {
    asm volatile("cp.async.commit_group;\n");
}
__device__ __forceinline__ void ldsm4(uint32_t* r, uint32_t a) {
    asm volatile("ldmatrix.sync.aligned.m8n8.x4.shared.b16 {%0,%1,%2,%3}, [%4];"
                 : "=r"(r[0]), "=r"(r[1]), "=r"(r[2]), "=r"(r[3]) : "r"(a));
}
__device__ __forceinline__ void ldsm4t(uint32_t* r, uint32_t a) {
    asm volatile("ldmatrix.sync.aligned.m8n8.x4.trans.shared.b16 {%0,%1,%2,%3}, [%4];"
                 : "=r"(r[0]), "=r"(r[1]), "=r"(r[2]), "=r"(r[3]) : "r"(a));
}
__device__ __forceinline__ void mma16816(float* d, const uint32_t* a, const uint32_t* b) {
    asm volatile("mma.sync.aligned.m16n8k16.row.col.f32.bf16.bf16.f32 "
        "{%0,%1,%2,%3}, {%4,%5,%6,%7}, {%8,%9}, {%0,%1,%2,%3};\n"
        : "+f"(d[0]), "+f"(d[1]), "+f"(d[2]), "+f"(d[3])
        : "r"(a[0]), "r"(a[1]), "r"(a[2]), "r"(a[3]), "r"(b[0]), "r"(b[1]));
}
__device__ __forceinline__ uint32_t packbf(float lo, float hi) {
    __nv_bfloat162 h = __floats2bfloat162_rn(lo, hi);
    return *reinterpret_cast<uint32_t*>(&h);
}
__device__ __forceinline__ float ex2(float x) {
    float y;
    asm("ex2.approx.ftz.f32 %0, %1;" : "=f"(y) : "f"(x));
    return y;
}

// ---------------- fused LayerNorm (ddof=1) + weight cvt ----------------
// cvt blocks: each thread converts 2 x float4 (8 floats) -> fewer blocks.
#define CVTBLKS (4 * DIM * DIM / (384 * 8))   // 768
__global__ void __launch_bounds__(384) ln_cvt(const float* __restrict__ x,
                                              __nv_bfloat16* __restrict__ xn,
                                              const float* __restrict__ w0,
                                              const float* __restrict__ w1,
                                              const float* __restrict__ w2,
                                              const float* __restrict__ w3,
                                              __nv_bfloat16* __restrict__ wb) {
    int t = threadIdx.x;
    if (blockIdx.x >= ROWS) {
        int i = ((blockIdx.x - ROWS) * 384 + t) * 8;      // [0, 4*DIM*DIM)
        int m = i / (DIM * DIM);                          // 8 | DIM*DIM, no straddle
        int r = i - m * (DIM * DIM);
        const float* s = m == 0 ? w0 : m == 1 ? w1 : m == 2 ? w2 : w3;
        float4 v0 = *(const float4*)(s + r);
        float4 v1 = *(const float4*)(s + r + 4);
        uint4 o;
        o.x = packbf(v0.x, v0.y);
        o.y = packbf(v0.z, v0.w);
        o.z = packbf(v1.x, v1.y);
        o.w = packbf(v1.z, v1.w);
        *(uint4*)(wb + i) = o;
        return;
    }
    int row = blockIdx.x;
    float2 v = *(const float2*)(x + (size_t)row * DIM + 2 * t);
    float s  = v.x + v.y;
    float sq = v.x * v.x + v.y * v.y;
    #pragma unroll
    for (int o = 16; o; o >>= 1) {
        s  += __shfl_xor_sync(0xffffffffu, s,  o);
        sq += __shfl_xor_sync(0xffffffffu, sq, o);
    }
    __shared__ float rs[12], rq[12];
    int w = t >> 5, l = t & 31;
    if (l == 0) { rs[w] = s; rq[w] = sq; }
    __syncthreads();
    if (w == 0) {
        s  = (l < 12) ? rs[l] : 0.f;
        sq = (l < 12) ? rq[l] : 0.f;
        #pragma unroll
        for (int o = 16; o; o >>= 1) {
            s  += __shfl_xor_sync(0xffffffffu, s,  o);
            sq += __shfl_xor_sync(0xffffffffu, sq, o);
        }
        if (l == 0) { rs[0] = s; rq[0] = sq; }
    }
    __syncthreads();
    s = rs[0]; sq = rq[0];
    float mean = s * (1.f / DIM);
    float var  = (sq - (float)DIM * mean * mean) * (1.f / (DIM - 1));
    float inv  = rsqrtf(var);
    ((uint32_t*)xn)[(size_t)row * (DIM / 2) + t] =
        packbf((v.x - mean) * inv, (v.y - mean) * inv);
}

// ---------------- bf16 GEMM-NT: BM=128 BN=64 BK=32, 3 CTAs/SM (R9 winner) ---
// 8 warps 4(m)x2(n), warp tile 32x32. 2-stage, one barrier per k-iter.
#define NKT (DIM / 32)            // 24
#define ASZ (128 * 40)            // A stage elems
#define BSZ (64 * 40)             // B stage elems
#define SMEM_GEMM (2 * (ASZ + BSZ) * 2)   // 30720 B
__global__ void __launch_bounds__(256, 3) gemm_bf(
        const __nv_bfloat16* __restrict__ A,
        const __nv_bfloat16* __restrict__ Wall,
        const float* __restrict__ b0, const float* __restrict__ b1,
        const float* __restrict__ b2,
        __nv_bfloat16* __restrict__ c0, __nv_bfloat16* __restrict__ c1,
        __nv_bfloat16* __restrict__ c2,
        const float* __restrict__ res, float* __restrict__ outF,
        int mode) {
    extern __shared__ __nv_bfloat16 gsm[];
    __nv_bfloat16* Asb = gsm;             // [2][128][40]
    __nv_bfloat16* Bsb = gsm + 2 * ASZ;   // [2][64][40]

    int nb, sel;
    if (mode == 0) { sel = blockIdx.x / 12; nb = blockIdx.x % 12; }
    else           { sel = 3;               nb = blockIdx.x; }
    const __nv_bfloat16* W = Wall + (size_t)sel * DIM * DIM;
    const float* bias = mode == 0 ? (sel == 0 ? b0 : sel == 1 ? b1 : b2) : b0;
    __nv_bfloat16* Cb = sel == 0 ? c0 : sel == 1 ? c1 : c2;
    float oscale = (mode == 0 && sel == 0) ? QSCALE : 1.0f;

    int bm0 = blockIdx.y * 128, bn0 = nb * 64;
    int tid = threadIdx.x, lane = tid & 31, wid = tid >> 5;
    int g = lane >> 2, tq = lane & 3;
    int wm = (wid >> 1) * 32, wn = (wid & 1) * 32;

    int lrA = tid >> 1, lkA = (tid & 1) * 16;   // A loader: 2 cp16/thr
    int lrB = tid >> 2, lkB = (tid & 3) * 8;    // B loader: 1 cp16/thr
    const __nv_bfloat16* Ag = A + (size_t)(bm0 + lrA) * DIM + lkA;
    const __nv_bfloat16* Wg = W + (size_t)(bn0 + lrB) * DIM + lkB;

    float acc[2][4][4] = {};

    // prefetch tile 0 into stage 0
    cp16(Asb + lrA * 40 + lkA,     Ag);
    cp16(Asb + lrA * 40 + lkA + 8, Ag + 8);
    cp16(Bsb + lrB * 40 + lkB,     Wg);
    cp_commit();

    for (int kt = 0; kt < NKT; kt++) {
        int s = kt & 1;
        asm volatile("cp.async.wait_group 0;\n");
        __syncthreads();   // tile kt visible; stage s^1 readers (kt-1) done
        if (kt + 1 < NKT) {
            cp16(Asb + (s ^ 1) * ASZ + lrA * 40 + lkA,     Ag + (kt + 1) * 32);
            cp16(Asb + (s ^ 1) * ASZ + lrA * 40 + lkA + 8, Ag + (kt + 1) * 32 + 8);
            cp16(Bsb + (s ^ 1) * BSZ + lrB * 40 + lkB,     Wg + (kt + 1) * 32);
            cp_commit();
        }

        uint32_t aA = saddr(Asb + s * ASZ + (wm + (lane & 15)) * 40
                            + (lane >> 4) * 8);
        uint32_t aB = saddr(Bsb + s * BSZ
                            + (wn + (lane & 7) + ((lane >> 4) & 1) * 8) * 40
                            + ((lane >> 3) & 1) * 8);
        #pragma unroll
        for (int ks = 0; ks < 2; ks++) {
            uint32_t a[2][4], b[2][4];
            #pragma unroll
            for (int mt = 0; mt < 2; mt++)
                ldsm4(a[mt], aA + mt * (16 * 80) + ks * 32);
            #pragma unroll
            for (int nt = 0; nt < 2; nt++)
                ldsm4(b[nt], aB + nt * (16 * 80) + ks * 32);
            #pragma unroll
            for (int mt = 0; mt < 2; mt++) {
                #pragma unroll
                for (int nt = 0; nt < 2; nt++) {
                    mma16816(acc[mt][2 * nt],     a[mt], b[nt]);
                    mma16816(acc[mt][2 * nt + 1], a[mt], b[nt] + 2);
                }
            }
        }
    }

    #pragma unroll
    for (int mt = 0; mt < 2; mt++) {
        int row = bm0 + wm + 16 * mt + g;
        #pragma unroll
        for (int j = 0; j < 4; j++) {
            int col = bn0 + wn + 8 * j + 2 * tq;
            float bx = bias[col], by = bias[col + 1];
            size_t o0 = (size_t)row * DIM + col;
            size_t o1 = (size_t)(row + 8) * DIM + col;
            if (mode == 0) {
                *(uint32_t*)(Cb + o0) = packbf((acc[mt][j][0] + bx) * oscale,
                                               (acc[mt][j][1] + by) * oscale);
                *(uint32_t*)(Cb + o1) = packbf((acc[mt][j][2] + bx) * oscale,
                                               (acc[mt][j][3] + by) * oscale);
            } else {
                float2 e0 = *(const float2*)(res + o0);
                float2 e1 = *(const float2*)(res + o1);
                *(float2*)(outF + o0) = make_float2(acc[mt][j][0] + bx + e0.x,
                                                    acc[mt][j][1] + by + e0.y);
                *(float2*)(outF + o1) = make_float2(acc[mt][j][2] + bx + e1.x,
                                                    acc[mt][j][3] + by + e1.y);
            }
        }
    }
}

// ---------------- bf16 flash attention: P in registers (R9 winner) ----------
#define KTILE 4608              // 64*72 elems
#define QTILE 9216              // 128*72 elems
#define SMEM_ATTN ((QTILE + 4 * KTILE) * 2)
__global__ void __launch_bounds__(256) attn_tc(const __nv_bfloat16* __restrict__ Q,
                                               const __nv_bfloat16* __restrict__ K,
                                               const __nv_bfloat16* __restrict__ V,
                                               __nv_bfloat16* __restrict__ O) {
    extern __shared__ __nv_bfloat16 smb[];
    __nv_bfloat16* sQ = smb;                       // 128 x 72
    __nv_bfloat16* sK = smb + QTILE;               // 2 x 64 x 72
    __nv_bfloat16* sV = smb + QTILE + 2 * KTILE;   // 2 x 64 x 72

    int qt = blockIdx.x, h = blockIdx.y, b = blockIdx.z;
    int tid = threadIdx.x, lane = tid & 31, wid = tid >> 5;
    int g = lane >> 2, tq = lane & 3;
    int m0 = wid * 16;

    int qlr = tid >> 1, qlk = (tid & 1) * 32;   // Q loader
    int klr = tid >> 2, klk = (tid & 3) * 16;   // K/V loader

    const __nv_bfloat16* Kg = K + (size_t)(b * SEQ + klr) * DIM + h * DH + klk;
    const __nv_bfloat16* Vg = V + (size_t)(b * SEQ + klr) * DIM + h * DH + klk;

    // Q tile copy (already scaled by QSCALE in GEMM)
    {
        const uint4* qp = (const uint4*)(Q + (size_t)(b * SEQ + qt * 128 + qlr) * DIM
                                           + h * DH + qlk);
        uint4* dq = (uint4*)&sQ[qlr * 72 + qlk];
        #pragma unroll
        for (int u = 0; u < 4; u++) dq[u] = qp[u];
    }

    // prefetch K/V tile 0 into stage 0
    cp16(&sK[klr * 72 + klk],     Kg);
    cp16(&sK[klr * 72 + klk + 8], Kg + 8);
    cp16(&sV[klr * 72 + klk],     Vg);
    cp16(&sV[klr * 72 + klk + 8], Vg + 8);
    cp_commit();

    uint32_t aQ = saddr(&sQ[(m0 + (lane & 15)) * 72 + (lane >> 4) * 8]);
    uint32_t aK0 = saddr(&sK[((lane & 7) + ((lane >> 4) & 1) * 8) * 72
                             + ((lane >> 3) & 1) * 8]);
    uint32_t aV0 = saddr(&sV[((lane & 7) + ((lane >> 3) & 1) * 8) * 72
                             + (lane >> 4) * 8]);

    __syncthreads();   // Q tile visible to all warps

    uint32_t qf[4][4];
    #pragma unroll
    for (int ks = 0; ks < 4; ks++) ldsm4(qf[ks], aQ + ks * 32);

    float m0r = -1e30f, m1r = -1e30f, l0r = 0.f, l1r = 0.f;
    float o[8][4] = {};

    for (int kt = 0; kt < SEQ / 64; kt++) {
        int s = kt & 1;
        asm volatile("cp.async.wait_group 0;\n");
        __syncthreads();   // stage s ready; stage s^1 readers (iter kt-1) done
        if (kt + 1 < SEQ / 64) {
            int so = (s ^ 1) * KTILE;
            const __nv_bfloat16* kg = Kg + (size_t)(kt + 1) * 64 * DIM;
            const __nv_bfloat16* vg = Vg + (size_t)(kt + 1) * 64 * DIM;
            cp16(&sK[so + klr * 72 + klk],     kg);
            cp16(&sK[so + klr * 72 + klk + 8], kg + 8);
            cp16(&sV[so + klr * 72 + klk],     vg);
            cp16(&sV[so + klr * 72 + klk + 8], vg + 8);
            cp_commit();
        }

        uint32_t aK = aK0 + s * (KTILE * 2);
        uint32_t aV = aV0 + s * (KTILE * 2);

        // S = Q K^T (warp's 16 rows x 64 keys); sc[j] = key cols 8j..8j+7
        float sc[8][4] = {};
        #pragma unroll
        for (int ks = 0; ks < 4; ks++) {
            #pragma unroll
            for (int j2 = 0; j2 < 4; j2++) {
                uint32_t bb[4];
                ldsm4(bb, aK + j2 * (16 * 144) + ks * 32);
                mma16816(sc[2 * j2],     qf[ks], bb);
                mma16816(sc[2 * j2 + 1], qf[ks], bb + 2);
            }
        }

        // online softmax, base-2 domain (Q pre-scaled by 0.125*log2e)
        float mx0 = -1e30f, mx1 = -1e30f;
        #pragma unroll
        for (int j = 0; j < 8; j++) {
            mx0 = fmaxf(mx0, fmaxf(sc[j][0], sc[j][1]));
            mx1 = fmaxf(mx1, fmaxf(sc[j][2], sc[j][3]));
        }
        mx0 = fmaxf(mx0, __shfl_xor_sync(0xffffffffu, mx0, 1));
        mx0 = fmaxf(mx0, __shfl_xor_sync(0xffffffffu, mx0, 2));
        mx1 = fmaxf(mx1, __shfl_xor_sync(0xffffffffu, mx1, 1));
        mx1 = fmaxf(mx1, __shfl_xor_sync(0xffffffffu, mx1, 2));
        float mn0 = fmaxf(m0r, mx0), mn1 = fmaxf(m1r, mx1);
        float al0 = ex2(m0r - mn0), al1 = ex2(m1r - mn1);
        float ls0 = 0.f, ls1 = 0.f;
        #pragma unroll
        for (int j = 0; j < 8; j++) {
            sc[j][0] = ex2(sc[j][0] - mn0); ls0 += sc[j][0];
            sc[j][1] = ex2(sc[j][1] - mn0); ls0 += sc[j][1];
            sc[j][2] = ex2(sc[j][2] - mn1); ls1 += sc[j][2];
            sc[j][3] = ex2(sc[j][3] - mn1); ls1 += sc[j][3];
        }
        ls0 += __shfl_xor_sync(0xffffffffu, ls0, 1);
        ls0 += __shfl_xor_sync(0xffffffffu, ls0, 2);
        ls1 += __shfl_xor_sync(0xffffffffu, ls1, 1);
        ls1 += __shfl_xor_sync(0xffffffffu, ls1, 2);
        l0r = l0r * al0 + ls0;  m0r = mn0;
        l1r = l1r * al1 + ls1;  m1r = mn1;
        #pragma unroll
        for (int j = 0; j < 8; j++) {
            o[j][0] *= al0; o[j][1] *= al0;
            o[j][2] *= al1; o[j][3] *= al1;
        }

        // O += P V : P packed straight from S fragments (no smem round-trip)
        #pragma unroll
        for (int ks = 0; ks < 4; ks++) {
            uint32_t a[4];
            a[0] = packbf(sc[2 * ks][0],     sc[2 * ks][1]);
            a[1] = packbf(sc[2 * ks][2],     sc[2 * ks][3]);
            a[2] = packbf(sc[2 * ks + 1][0], sc[2 * ks + 1][1]);
            a[3] = packbf(sc[2 * ks + 1][2], sc[2 * ks + 1][3]);
            #pragma unroll
            for (int j2 = 0; j2 < 4; j2++) {
                uint32_t bb[4];
                ldsm4t(bb, aV + ks * (16 * 144) + j2 * 32);
                mma16816(o[2 * j2],     a, bb);
                mma16816(o[2 * j2 + 1], a, bb + 2);
            }
        }
    }

    float inv0 = 1.f / l0r, inv1 = 1.f / l1r;
    int row0 = b * SEQ + qt * 128 + m0 + g;
    #pragma unroll
    for (int j = 0; j < 8; j++) {
        int col = h * DH + 8 * j + 2 * tq;
        *(uint32_t*)(O + (size_t)row0 * DIM + col) =
            packbf(o[j][0] * inv0, o[j][1] * inv0);
        *(uint32_t*)(O + (size_t)(row0 + 8) * DIM + col) =
            packbf(o[j][2] * inv1, o[j][3] * inv1);
    }
}

// ---------------- launch ----------------
extern "C" void kernel_launch(void* const* d_in, const int* in_sizes, int n_in,
                              void* d_out, int out_size) {
    const float* x  = (const float*)d_in[0];
    const float* qw = (const float*)d_in[1];
    const float* kw = (const float*)d_in[2];
    const float* vw = (const float*)d_in[3];
    const float* qb = (const float*)d_in[4];
    const float* kb = (const float*)d_in[5];
    const float* vb = (const float*)d_in[6];
    const float* pw = (const float*)d_in[7];
    const float* pb = (const float*)d_in[8];
    float* out = (float*)d_out;

    __nv_bfloat16 *xn, *q, *k, *v, *att, *wb;
    cudaGetSymbolAddress((void**)&xn,  g_xn);
    cudaGetSymbolAddress((void**)&q,   g_q);
    cudaGetSymbolAddress((void**)&k,   g_k);
    cudaGetSymbolAddress((void**)&v,   g_v);
    cudaGetSymbolAddress((void**)&att, g_att);
    cudaGetSymbolAddress((void**)&wb,  g_wb);

    cudaFuncSetAttribute(attn_tc,
                         cudaFuncAttributeMaxDynamicSharedMemorySize, SMEM_ATTN);
    cudaFuncSetAttribute(gemm_bf,
                         cudaFuncAttributeMaxDynamicSharedMemorySize, SMEM_GEMM);

    // fused LayerNorm + weight conversion
    ln_cvt<<<ROWS + CVTBLKS, 384>>>(x, xn, qw, kw, vw, pw, wb);

    // QKV: 36 x 32 blocks (sel = x/12); q output pre-scaled by QSCALE
    gemm_bf<<<dim3(36, 32), 256, SMEM_GEMM>>>(xn, wb, qb, kb, vb, q, k, v,
                                              nullptr, nullptr, 0);

    attn_tc<<<dim3(SEQ / 128, NH, BATCH), 256, SMEM_ATTN>>>(q, k, v, att);

    // proj: 12 x 32 blocks, fp32 out + bias + residual
    gemm_bf<<<dim3(12, 32), 256, SMEM_GEMM>>>(att, wb, pb, nullptr, nullptr,
                                              nullptr, nullptr, nullptr, x, out, 1);
}

// round 17
// speedup vs baseline: 1.2063x; 1.0149x over previous
#include <cuda_runtime.h>
#include <cuda_bf16.h>
#include <cstdint>

#define DIM 768
#define NH 12
#define DH 64
#define BATCH 4
#define SEQ 1024
#define ROWS (BATCH*SEQ)            // 4096
#define QSCALE 0.18033688011112042f // 0.125 * log2(e), folded into Q epilogue

// ---------------- scratch ----------------
__device__ __nv_bfloat16 g_xn [ROWS*DIM];
__device__ __nv_bfloat16 g_q  [ROWS*DIM];
__device__ __nv_bfloat16 g_k  [ROWS*DIM];
__device__ __nv_bfloat16 g_v  [ROWS*DIM];
__device__ __nv_bfloat16 g_att[ROWS*DIM];
__device__ __nv_bfloat16 g_wb [4 * DIM * DIM];   // bf16 weights: q,k,v,proj

// ---------------- helpers ----------------
__device__ __forceinline__ uint32_t saddr(const void* p) {
    return (uint32_t)__cvta_generic_to_shared(p);
}
__device__ __forceinline__ void cp16(void* s, const void* g) {
    asm volatile("cp.async.cg.shared.global [%0], [%1], 16;\n"
                 :: "r"(saddr(s)), "l"(g));
}
__device__ __forceinline__ void cp_commit() {
    asm volatile("cp.async.commit_group;\n");
}
__device__ __forceinline__ void ldsm4(uint32_t* r, uint32_t a) {
    asm volatile("ldmatrix.sync.aligned.m8n8.x4.shared.b16 {%0,%1,%2,%3}, [%4];"
                 : "=r"(r[0]), "=r"(r[1]), "=r"(r[2]), "=r"(r[3]) : "r"(a));
}
__device__ __forceinline__ void ldsm4t(uint32_t* r, uint32_t a) {
    asm volatile("ldmatrix.sync.aligned.m8n8.x4.trans.shared.b16 {%0,%1,%2,%3}, [%4];"
                 : "=r"(r[0]), "=r"(r[1]), "=r"(r[2]), "=r"(r[3]) : "r"(a));
}
__device__ __forceinline__ void mma16816(float* d, const uint32_t* a, const uint32_t* b) {
    asm volatile("mma.sync.aligned.m16n8k16.row.col.f32.bf16.bf16.f32 "
        "{%0,%1,%2,%3}, {%4,%5,%6,%7}, {%8,%9}, {%0,%1,%2,%3};\n"
        : "+f"(d[0]), "+f"(d[1]), "+f"(d[2]), "+f"(d[3])
        : "r"(a[0]), "r"(a[1]), "r"(a[2]), "r"(a[3]), "r"(b[0]), "r"(b[1]));
}
__device__ __forceinline__ uint32_t packbf(float lo, float hi) {
    __nv_bfloat162 h = __floats2bfloat162_rn(lo, hi);
    return *reinterpret_cast<uint32_t*>(&h);
}
__device__ __forceinline__ float ex2(float x) {
    float y;
    asm("ex2.approx.ftz.f32 %0, %1;" : "=f"(y) : "f"(x));
    return y;
}

// ---------------- fused LayerNorm (ddof=1, 2 rows/block) + weight cvt -------
#define LNBLKS (ROWS / 2)                     // 2048
#define CVTBLKS (4 * DIM * DIM / (384 * 8))   // 768
__global__ void __launch_bounds__(384) ln_cvt(const float* __restrict__ x,
                                              __nv_bfloat16* __restrict__ xn,
                                              const float* __restrict__ w0,
                                              const float* __restrict__ w1,
                                              const float* __restrict__ w2,
                                              const float* __restrict__ w3,
                                              __nv_bfloat16* __restrict__ wb) {
    int t = threadIdx.x;
    if (blockIdx.x >= LNBLKS) {
        int i = ((blockIdx.x - LNBLKS) * 384 + t) * 8;    // [0, 4*DIM*DIM)
        int m = i / (DIM * DIM);                          // 8 | DIM*DIM, no straddle
        int r = i - m * (DIM * DIM);
        const float* s = m == 0 ? w0 : m == 1 ? w1 : m == 2 ? w2 : w3;
        float4 v0 = *(const float4*)(s + r);
        float4 v1 = *(const float4*)(s + r + 4);
        uint4 o;
        o.x = packbf(v0.x, v0.y);
        o.y = packbf(v0.z, v0.w);
        o.z = packbf(v1.x, v1.y);
        o.w = packbf(v1.z, v1.w);
        *(uint4*)(wb + i) = o;
        return;
    }
    __shared__ float rs[12], rq[12];
    int w = t >> 5, l = t & 31;
    #pragma unroll
    for (int r = 0; r < 2; r++) {
        int row = blockIdx.x * 2 + r;
        float2 v = *(const float2*)(x + (size_t)row * DIM + 2 * t);
        float s  = v.x + v.y;
        float sq = v.x * v.x + v.y * v.y;
        #pragma unroll
        for (int o = 16; o; o >>= 1) {
            s  += __shfl_xor_sync(0xffffffffu, s,  o);
            sq += __shfl_xor_sync(0xffffffffu, sq, o);
        }
        if (l == 0) { rs[w] = s; rq[w] = sq; }
        __syncthreads();
        if (w == 0) {
            s  = (l < 12) ? rs[l] : 0.f;
            sq = (l < 12) ? rq[l] : 0.f;
            #pragma unroll
            for (int o = 16; o; o >>= 1) {
                s  += __shfl_xor_sync(0xffffffffu, s,  o);
                sq += __shfl_xor_sync(0xffffffffu, sq, o);
            }
            if (l == 0) { rs[0] = s; rq[0] = sq; }
        }
        __syncthreads();
        s = rs[0]; sq = rq[0];
        float mean = s * (1.f / DIM);
        float var  = (sq - (float)DIM * mean * mean) * (1.f / (DIM - 1));
        float inv  = rsqrtf(var);
        ((uint32_t*)xn)[(size_t)row * (DIM / 2) + t] =
            packbf((v.x - mean) * inv, (v.y - mean) * inv);
        __syncthreads();   // rs/rq reuse fence before next row
    }
}

// ---------------- bf16 GEMM-NT: BM=128 BN=64 BK=32, 3 CTAs/SM (R9 winner) ---
// 8 warps 4(m)x2(n), warp tile 32x32. 2-stage, one barrier per k-iter.
#define NKT (DIM / 32)            // 24
#define ASZ (128 * 40)            // A stage elems
#define BSZ (64 * 40)             // B stage elems
#define SMEM_GEMM (2 * (ASZ + BSZ) * 2)   // 30720 B
__global__ void __launch_bounds__(256, 3) gemm_bf(
        const __nv_bfloat16* __restrict__ A,
        const __nv_bfloat16* __restrict__ Wall,
        const float* __restrict__ b0, const float* __restrict__ b1,
        const float* __restrict__ b2,
        __nv_bfloat16* __restrict__ c0, __nv_bfloat16* __restrict__ c1,
        __nv_bfloat16* __restrict__ c2,
        const float* __restrict__ res, float* __restrict__ outF,
        int mode) {
    extern __shared__ __nv_bfloat16 gsm[];
    __nv_bfloat16* Asb = gsm;             // [2][128][40]
    __nv_bfloat16* Bsb = gsm + 2 * ASZ;   // [2][64][40]

    int nb, sel;
    if (mode == 0) { sel = blockIdx.x / 12; nb = blockIdx.x % 12; }
    else           { sel = 3;               nb = blockIdx.x; }
    const __nv_bfloat16* W = Wall + (size_t)sel * DIM * DIM;
    const float* bias = mode == 0 ? (sel == 0 ? b0 : sel == 1 ? b1 : b2) : b0;
    __nv_bfloat16* Cb = sel == 0 ? c0 : sel == 1 ? c1 : c2;
    float oscale = (mode == 0 && sel == 0) ? QSCALE : 1.0f;

    int bm0 = blockIdx.y * 128, bn0 = nb * 64;
    int tid = threadIdx.x, lane = tid & 31, wid = tid >> 5;
    int g = lane >> 2, tq = lane & 3;
    int wm = (wid >> 1) * 32, wn = (wid & 1) * 32;

    int lrA = tid >> 1, lkA = (tid & 1) * 16;   // A loader: 2 cp16/thr
    int lrB = tid >> 2, lkB = (tid & 3) * 8;    // B loader: 1 cp16/thr
    const __nv_bfloat16* Ag = A + (size_t)(bm0 + lrA) * DIM + lkA;
    const __nv_bfloat16* Wg = W + (size_t)(bn0 + lrB) * DIM + lkB;

    float acc[2][4][4] = {};

    // prefetch tile 0 into stage 0
    cp16(Asb + lrA * 40 + lkA,     Ag);
    cp16(Asb + lrA * 40 + lkA + 8, Ag + 8);
    cp16(Bsb + lrB * 40 + lkB,     Wg);
    cp_commit();

    for (int kt = 0; kt < NKT; kt++) {
        int s = kt & 1;
        asm volatile("cp.async.wait_group 0;\n");
        __syncthreads();   // tile kt visible; stage s^1 readers (kt-1) done
        if (kt + 1 < NKT) {
            cp16(Asb + (s ^ 1) * ASZ + lrA * 40 + lkA,     Ag + (kt + 1) * 32);
            cp16(Asb + (s ^ 1) * ASZ + lrA * 40 + lkA + 8, Ag + (kt + 1) * 32 + 8);
            cp16(Bsb + (s ^ 1) * BSZ + lrB * 40 + lkB,     Wg + (kt + 1) * 32);
            cp_commit();
        }

        uint32_t aA = saddr(Asb + s * ASZ + (wm + (lane & 15)) * 40
                            + (lane >> 4) * 8);
        uint32_t aB = saddr(Bsb + s * BSZ
                            + (wn + (lane & 7) + ((lane >> 4) & 1) * 8) * 40
                            + ((lane >> 3) & 1) * 8);
        #pragma unroll
        for (int ks = 0; ks < 2; ks++) {
            uint32_t a[2][4], b[2][4];
            #pragma unroll
            for (int mt = 0; mt < 2; mt++)
                ldsm4(a[mt], aA + mt * (16 * 80) + ks * 32);
            #pragma unroll
            for (int nt = 0; nt < 2; nt++)
                ldsm4(b[nt], aB + nt * (16 * 80) + ks * 32);
            #pragma unroll
            for (int mt = 0; mt < 2; mt++) {
                #pragma unroll
                for (int nt = 0; nt < 2; nt++) {
                    mma16816(acc[mt][2 * nt],     a[mt], b[nt]);
                    mma16816(acc[mt][2 * nt + 1], a[mt], b[nt] + 2);
                }
            }
        }
    }

    #pragma unroll
    for (int mt = 0; mt < 2; mt++) {
        int row = bm0 + wm + 16 * mt + g;
        #pragma unroll
        for (int j = 0; j < 4; j++) {
            int col = bn0 + wn + 8 * j + 2 * tq;
            float bx = bias[col], by = bias[col + 1];
            size_t o0 = (size_t)row * DIM + col;
            size_t o1 = (size_t)(row + 8) * DIM + col;
            if (mode == 0) {
                *(uint32_t*)(Cb + o0) = packbf((acc[mt][j][0] + bx) * oscale,
                                               (acc[mt][j][1] + by) * oscale);
                *(uint32_t*)(Cb + o1) = packbf((acc[mt][j][2] + bx) * oscale,
                                               (acc[mt][j][3] + by) * oscale);
            } else {
                float2 e0 = *(const float2*)(res + o0);
                float2 e1 = *(const float2*)(res + o1);
                *(float2*)(outF + o0) = make_float2(acc[mt][j][0] + bx + e0.x,
                                                    acc[mt][j][1] + by + e0.y);
                *(float2*)(outF + o1) = make_float2(acc[mt][j][2] + bx + e1.x,
                                                    acc[mt][j][3] + by + e1.y);
            }
        }
    }
}

// ---------------- bf16 flash attention: P in registers (R9 winner) ----------
#define KTILE 4608              // 64*72 elems
#define QTILE 9216              // 128*72 elems
#define SMEM_ATTN ((QTILE + 4 * KTILE) * 2)
__global__ void __launch_bounds__(256) attn_tc(const __nv_bfloat16* __restrict__ Q,
                                               const __nv_bfloat16* __restrict__ K,
                                               const __nv_bfloat16* __restrict__ V,
                                               __nv_bfloat16* __restrict__ O) {
    extern __shared__ __nv_bfloat16 smb[];
    __nv_bfloat16* sQ = smb;                       // 128 x 72
    __nv_bfloat16* sK = smb + QTILE;               // 2 x 64 x 72
    __nv_bfloat16* sV = smb + QTILE + 2 * KTILE;   // 2 x 64 x 72

    int qt = blockIdx.x, h = blockIdx.y, b = blockIdx.z;
    int tid = threadIdx.x, lane = tid & 31, wid = tid >> 5;
    int g = lane >> 2, tq = lane & 3;
    int m0 = wid * 16;

    int qlr = tid >> 1, qlk = (tid & 1) * 32;   // Q loader
    int klr = tid >> 2, klk = (tid & 3) * 16;   // K/V loader

    const __nv_bfloat16* Kg = K + (size_t)(b * SEQ + klr) * DIM + h * DH + klk;
    const __nv_bfloat16* Vg = V + (size_t)(b * SEQ + klr) * DIM + h * DH + klk;

    // Q tile copy (already scaled by QSCALE in GEMM)
    {
        const uint4* qp = (const uint4*)(Q + (size_t)(b * SEQ + qt * 128 + qlr) * DIM
                                           + h * DH + qlk);
        uint4* dq = (uint4*)&sQ[qlr * 72 + qlk];
        #pragma unroll
        for (int u = 0; u < 4; u++) dq[u] = qp[u];
    }

    // prefetch K/V tile 0 into stage 0
    cp16(&sK[klr * 72 + klk],     Kg);
    cp16(&sK[klr * 72 + klk + 8], Kg + 8);
    cp16(&sV[klr * 72 + klk],     Vg);
    cp16(&sV[klr * 72 + klk + 8], Vg + 8);
    cp_commit();

    uint32_t aQ = saddr(&sQ[(m0 + (lane & 15)) * 72 + (lane >> 4) * 8]);
    uint32_t aK0 = saddr(&sK[((lane & 7) + ((lane >> 4) & 1) * 8) * 72
                             + ((lane >> 3) & 1) * 8]);
    uint32_t aV0 = saddr(&sV[((lane & 7) + ((lane >> 3) & 1) * 8) * 72
                             + (lane >> 4) * 8]);

    __syncthreads();   // Q tile visible to all warps

    uint32_t qf[4][4];
    #pragma unroll
    for (int ks = 0; ks < 4; ks++) ldsm4(qf[ks], aQ + ks * 32);

    float m0r = -1e30f, m1r = -1e30f, l0r = 0.f, l1r = 0.f;
    float o[8][4] = {};

    for (int kt = 0; kt < SEQ / 64; kt++) {
        int s = kt & 1;
        asm volatile("cp.async.wait_group 0;\n");
        __syncthreads();   // stage s ready; stage s^1 readers (iter kt-1) done
        if (kt + 1 < SEQ / 64) {
            int so = (s ^ 1) * KTILE;
            const __nv_bfloat16* kg = Kg + (size_t)(kt + 1) * 64 * DIM;
            const __nv_bfloat16* vg = Vg + (size_t)(kt + 1) * 64 * DIM;
            cp16(&sK[so + klr * 72 + klk],     kg);
            cp16(&sK[so + klr * 72 + klk + 8], kg + 8);
            cp16(&sV[so + klr * 72 + klk],     vg);
            cp16(&sV[so + klr * 72 + klk + 8], vg + 8);
            cp_commit();
        }

        uint32_t aK = aK0 + s * (KTILE * 2);
        uint32_t aV = aV0 + s * (KTILE * 2);

        // S = Q K^T (warp's 16 rows x 64 keys); sc[j] = key cols 8j..8j+7
        float sc[8][4] = {};
        #pragma unroll
        for (int ks = 0; ks < 4; ks++) {
            #pragma unroll
            for (int j2 = 0; j2 < 4; j2++) {
                uint32_t bb[4];
                ldsm4(bb, aK + j2 * (16 * 144) + ks * 32);
                mma16816(sc[2 * j2],     qf[ks], bb);
                mma16816(sc[2 * j2 + 1], qf[ks], bb + 2);
            }
        }

        // online softmax, base-2 domain (Q pre-scaled by 0.125*log2e)
        float mx0 = -1e30f, mx1 = -1e30f;
        #pragma unroll
        for (int j = 0; j < 8; j++) {
            mx0 = fmaxf(mx0, fmaxf(sc[j][0], sc[j][1]));
            mx1 = fmaxf(mx1, fmaxf(sc[j][2], sc[j][3]));
        }
        mx0 = fmaxf(mx0, __shfl_xor_sync(0xffffffffu, mx0, 1));
        mx0 = fmaxf(mx0, __shfl_xor_sync(0xffffffffu, mx0, 2));
        mx1 = fmaxf(mx1, __shfl_xor_sync(0xffffffffu, mx1, 1));
        mx1 = fmaxf(mx1, __shfl_xor_sync(0xffffffffu, mx1, 2));
        float mn0 = fmaxf(m0r, mx0), mn1 = fmaxf(m1r, mx1);
        float al0 = ex2(m0r - mn0), al1 = ex2(m1r - mn1);
        float ls0 = 0.f, ls1 = 0.f;
        #pragma unroll
        for (int j = 0; j < 8; j++) {
            sc[j][0] = ex2(sc[j][0] - mn0); ls0 += sc[j][0];
            sc[j][1] = ex2(sc[j][1] - mn0); ls0 += sc[j][1];
            sc[j][2] = ex2(sc[j][2] - mn1); ls1 += sc[j][2];
            sc[j][3] = ex2(sc[j][3] - mn1); ls1 += sc[j][3];
        }
        ls0 += __shfl_xor_sync(0xffffffffu, ls0, 1);
        ls0 += __shfl_xor_sync(0xffffffffu, ls0, 2);
        ls1 += __shfl_xor_sync(0xffffffffu, ls1, 1);
        ls1 += __shfl_xor_sync(0xffffffffu, ls1, 2);
        l0r = l0r * al0 + ls0;  m0r = mn0;
        l1r = l1r * al1 + ls1;  m1r = mn1;
        #pragma unroll
        for (int j = 0; j < 8; j++) {
            o[j][0] *= al0; o[j][1] *= al0;
            o[j][2] *= al1; o[j][3] *= al1;
        }

        // O += P V : P packed straight from S fragments (no smem round-trip)
        #pragma unroll
        for (int ks = 0; ks < 4; ks++) {
            uint32_t a[4];
            a[0] = packbf(sc[2 * ks][0],     sc[2 * ks][1]);
            a[1] = packbf(sc[2 * ks][2],     sc[2 * ks][3]);
            a[2] = packbf(sc[2 * ks + 1][0], sc[2 * ks + 1][1]);
            a[3] = packbf(sc[2 * ks + 1][2], sc[2 * ks + 1][3]);
            #pragma unroll
            for (int j2 = 0; j2 < 4; j2++) {
                uint32_t bb[4];
                ldsm4t(bb, aV + ks * (16 * 144) + j2 * 32);
                mma16816(o[2 * j2],     a, bb);
                mma16816(o[2 * j2 + 1], a, bb + 2);
            }
        }
    }

    float inv0 = 1.f / l0r, inv1 = 1.f / l1r;
    int row0 = b * SEQ + qt * 128 + m0 + g;
    #pragma unroll
    for (int j = 0; j < 8; j++) {
        int col = h * DH + 8 * j + 2 * tq;
        *(uint32_t*)(O + (size_t)row0 * DIM + col) =
            packbf(o[j][0] * inv0, o[j][1] * inv0);
        *(uint32_t*)(O + (size_t)(row0 + 8) * DIM + col) =
            packbf(o[j][2] * inv1, o[j][3] * inv1);
    }
}

// ---------------- launch ----------------
extern "C" void kernel_launch(void* const* d_in, const int* in_sizes, int n_in,
                              void* d_out, int out_size) {
    const float* x  = (const float*)d_in[0];
    const float* qw = (const float*)d_in[1];
    const float* kw = (const float*)d_in[2];
    const float* vw = (const float*)d_in[3];
    const float* qb = (const float*)d_in[4];
    const float* kb = (const float*)d_in[5];
    const float* vb = (const float*)d_in[6];
    const float* pw = (const float*)d_in[7];
    const float* pb = (const float*)d_in[8];
    float* out = (float*)d_out;

    __nv_bfloat16 *xn, *q, *k, *v, *att, *wb;
    cudaGetSymbolAddress((void**)&xn,  g_xn);
    cudaGetSymbolAddress((void**)&q,   g_q);
    cudaGetSymbolAddress((void**)&k,   g_k);
    cudaGetSymbolAddress((void**)&v,   g_v);
    cudaGetSymbolAddress((void**)&att, g_att);
    cudaGetSymbolAddress((void**)&wb,  g_wb);

    cudaFuncSetAttribute(attn_tc,
                         cudaFuncAttributeMaxDynamicSharedMemorySize, SMEM_ATTN);
    cudaFuncSetAttribute(gemm_bf,
                         cudaFuncAttributeMaxDynamicSharedMemorySize, SMEM_GEMM);

    // fused LayerNorm (2 rows/block) + weight conversion
    ln_cvt<<<LNBLKS + CVTBLKS, 384>>>(x, xn, qw, kw, vw, pw, wb);

    // QKV: 36 x 32 blocks (sel = x/12); q output pre-scaled by QSCALE
    gemm_bf<<<dim3(36, 32), 256, SMEM_GEMM>>>(xn, wb, qb, kb, vb, q, k, v,
                                              nullptr, nullptr, 0);

    attn_tc<<<dim3(SEQ / 128, NH, BATCH), 256, SMEM_ATTN>>>(q, k, v, att);

    // proj: 12 x 32 blocks, fp32 out + bias + residual
    gemm_bf<<<dim3(12, 32), 256, SMEM_GEMM>>>(att, wb, pb, nullptr, nullptr,
                                              nullptr, nullptr, nullptr, x, out, 1);
}